// round 3
// baseline (speedup 1.0000x reference)
#include <cuda_runtime.h>

// ============================================================================
// SphericalHarmonicsGaussianKernels
//   patches: (8, 2048, 32, 3) fp32   -> d_in[0]
//   Y:       (16, 20) fp32           -> d_in[1]
//   out:     (8, 2048, 32, 16, 4) fp32
//
// R3 changes vs R2 (90.1us):
//   k_out:    smem-stage each warp's 32x64-float tile, store coalesced
//             (fixes L1-bound strided STG: 32 lines/instr -> 4 lines/instr)
//   k_reduce: 8 points/thread, butterfly over 4 lanes only (80->4 SHFL/point)
// ============================================================================

__device__ float g_acc[128];      // [b][l*4+s]
__device__ float g_ninv[128];     // [b][l*4+s]

// ---------------------------------------------------------------------------
// Per-point evaluation: sh[16] (Y . monomials) and shn[4] (normalized, masked
// gaussian shells). sY = Y in shared memory, row-major [16][20].
// Monomial order = sorted lexicographic (i,j,k), i = x-exponent:
//  0:1  1:z  2:z2  3:z3  4:y  5:yz  6:yz2  7:y2  8:y2z  9:y3
// 10:x 11:xz 12:xz2 13:xy 14:xyz 15:xy2 16:x2 17:x2z 18:x2y 19:x3
// ---------------------------------------------------------------------------
__device__ __forceinline__ void point_eval(const float* __restrict__ sY,
                                           float x, float y, float z,
                                           float sh[16], float shn[4]) {
    float r2   = fmaf(x, x, fmaf(y, y, z * z));
    float dist = sqrtf(r2);
    float inv  = 1.0f / fmaxf(dist, 1e-6f);
    float nx = -x * inv, ny = -y * inv, nz = -z * inv;

    float mono[20];
    mono[0]  = 1.0f;
    mono[1]  = nz;
    mono[2]  = nz * nz;
    mono[3]  = mono[2] * nz;
    mono[4]  = ny;
    mono[5]  = ny * nz;
    mono[6]  = ny * mono[2];
    mono[7]  = ny * ny;
    mono[8]  = mono[7] * nz;
    mono[9]  = mono[7] * ny;
    mono[10] = nx;
    mono[11] = nx * nz;
    mono[12] = nx * mono[2];
    mono[13] = nx * ny;
    mono[14] = mono[13] * nz;
    mono[15] = nx * mono[7];
    mono[16] = nx * nx;
    mono[17] = mono[16] * nz;
    mono[18] = mono[16] * ny;
    mono[19] = mono[16] * nx;

    #pragma unroll
    for (int m = 0; m < 16; m++) {
        float a = sY[m * 20];                 // mono[0] == 1
        #pragma unroll
        for (int t = 1; t < 20; t++)
            a = fmaf(sY[m * 20 + t], mono[t], a);
        sh[m] = a;
    }

    float e[4];
    float ssum = 0.0f;
    #pragma unroll
    for (int s = 0; s < 4; s++) {
        float d = dist - (float)s * (1.0f / 3.0f);
        e[s] = __expf(-16.0f * d * d);
        ssum += e[s];
    }
    float w = 1.0f / fmaxf(ssum, 1e-6f);
    if (dist > 1.0f) w = 0.0f;                // mask AFTER normalization (ref order)
    #pragma unroll
    for (int s = 0; s < 4; s++) shn[s] = e[s] * w;
}

// ---------------------------------------------------------------------------
__global__ void k_zero() {
    g_acc[threadIdx.x] = 0.0f;                // 128 threads
}

// ---------------------------------------------------------------------------
// k_reduce: 256 blocks x 256 threads. Warp handles 8 v's; each thread handles
// 8 contiguous points of one v (4 lanes per v). Butterfly over off={1,2}.
// b = blockIdx.x >> 5 (32 blocks per batch, batch-aligned).
// ---------------------------------------------------------------------------
__global__ __launch_bounds__(256) void k_reduce(const float* __restrict__ patches,
                                                const float* __restrict__ Y) {
    __shared__ float sY[320];
    __shared__ float bacc[16];
    int tid = threadIdx.x;
    if (tid < 16)  bacc[tid] = 0.0f;
    for (int i = tid; i < 320; i += 256) sY[i] = Y[i];
    __syncthreads();

    int warp = tid >> 5;
    int lane = tid & 31;
    int v    = blockIdx.x * 64 + warp * 8 + (lane >> 2);
    int sub  = lane & 3;

    // 8 points = 24 floats = 6 float4, 16B-aligned (v*96 + sub*24 floats)
    const float4* pb = (const float4*)patches + (size_t)v * 24 + sub * 6;
    float4 f0 = pb[0], f1 = pb[1], f2 = pb[2], f3 = pb[3], f4 = pb[4], f5 = pb[5];
    float pf[24] = { f0.x,f0.y,f0.z,f0.w, f1.x,f1.y,f1.z,f1.w,
                     f2.x,f2.y,f2.z,f2.w, f3.x,f3.y,f3.z,f3.w,
                     f4.x,f4.y,f4.z,f4.w, f5.x,f5.y,f5.z,f5.w };

    float c[16];
    #pragma unroll
    for (int i = 0; i < 16; i++) c[i] = 0.0f;

    #pragma unroll
    for (int j = 0; j < 8; j++) {
        float sh[16], shn[4];
        point_eval(sY, pf[3*j], pf[3*j+1], pf[3*j+2], sh, shn);

        float q[4];
        q[0] = sh[0] * sh[0];
        q[1] = fmaf(sh[1], sh[1], fmaf(sh[2], sh[2], sh[3] * sh[3]));
        q[2] = fmaf(sh[4], sh[4], fmaf(sh[5], sh[5],
               fmaf(sh[6], sh[6], fmaf(sh[7], sh[7], sh[8] * sh[8]))));
        q[3] = fmaf(sh[9],  sh[9],  fmaf(sh[10], sh[10],
               fmaf(sh[11], sh[11], fmaf(sh[12], sh[12],
               fmaf(sh[13], sh[13], fmaf(sh[14], sh[14], sh[15] * sh[15]))))));

        float s2[4];
        #pragma unroll
        for (int s = 0; s < 4; s++) s2[s] = shn[s] * shn[s];
        #pragma unroll
        for (int l = 0; l < 4; l++)
            #pragma unroll
            for (int s = 0; s < 4; s++)
                c[l * 4 + s] = fmaf(q[l], s2[s], c[l * 4 + s]);
    }

    // sum over the 4 lanes of this v
    #pragma unroll
    for (int off = 1; off <= 2; off <<= 1) {
        #pragma unroll
        for (int i = 0; i < 16; i++)
            c[i] += __shfl_xor_sync(0xffffffffu, c[i], off);
    }

    if (sub == 0) {
        #pragma unroll
        for (int i = 0; i < 16; i++)
            atomicAdd(&bacc[i], sqrtf(c[i]));   // sqrt per v, BEFORE mean over v
    }
    __syncthreads();

    if (tid < 16) {
        int b = blockIdx.x >> 5;
        atomicAdd(&g_acc[b * 16 + tid], bacc[tid]);
    }
}

__global__ void k_finalize() {
    int t = threadIdx.x;                      // 128 threads
    float ml = g_acc[t] * (1.0f / 2048.0f);
    g_ninv[t] = 1.0f / fmaxf(ml, 1e-8f);
}

// ---------------------------------------------------------------------------
// k_out: 4096 blocks x 128 threads. One thread per point; warp stages its
// 32x64-float tile in smem ([16 m][33] float4, pad -> conflict-free), then
// streams it out lane-consecutive (512B contiguous per STG.128).
// b = blockIdx.x >> 9 (512 blocks per batch, batch-aligned).
// ---------------------------------------------------------------------------
__global__ __launch_bounds__(128) void k_out(const float* __restrict__ patches,
                                             const float* __restrict__ Y,
                                             float* __restrict__ out) {
    __shared__ float  sY[320];
    __shared__ float  sninv[16];
    __shared__ float4 stage[4][16 * 33];      // [warp][m*33 + p]
    int tid = threadIdx.x;
    if (tid < 16) {
        int b = blockIdx.x >> 9;
        sninv[tid] = g_ninv[b * 16 + tid];
    }
    for (int i = tid; i < 320; i += 128) sY[i] = Y[i];
    __syncthreads();

    int warp = tid >> 5;
    int lane = tid & 31;
    int pt   = blockIdx.x * 128 + tid;

    const float* p = patches + (size_t)pt * 3;
    float x = p[0], y = p[1], z = p[2];

    float sh[16], shn[4];
    point_eval(sY, x, y, z, sh, shn);

    float gls[16];
    #pragma unroll
    for (int l = 0; l < 4; l++) {
        #pragma unroll
        for (int s = 0; s < 4; s++)
            gls[l * 4 + s] = shn[s] * sninv[l * 4 + s];
    }

    float4* st = &stage[warp][0];
    #pragma unroll
    for (int m = 0; m < 16; m++) {
        const int l = (m == 0) ? 0 : (m < 4) ? 1 : (m < 9) ? 2 : 3;
        float4 v;
        v.x = sh[m] * gls[l * 4 + 0];
        v.y = sh[m] * gls[l * 4 + 1];
        v.z = sh[m] * gls[l * 4 + 2];
        v.w = sh[m] * gls[l * 4 + 3];
        st[m * 33 + lane] = v;
    }
    __syncwarp();

    // warp's 32 points = 512 float4 contiguous in gmem
    float4* dst = (float4*)out + ((size_t)blockIdx.x * 128 + warp * 32) * 16;
    #pragma unroll
    for (int it = 0; it < 16; it++) {
        int f = it * 32 + lane;
        int pp = f >> 4;
        int m  = f & 15;
        dst[f] = st[m * 33 + pp];
    }
}

// ---------------------------------------------------------------------------
extern "C" void kernel_launch(void* const* d_in, const int* in_sizes, int n_in,
                              void* d_out, int out_size) {
    const float* patches = (const float*)d_in[0];
    const float* Y       = (const float*)d_in[1];
    float*       out     = (float*)d_out;

    k_zero<<<1, 128>>>();
    k_reduce<<<256, 256>>>(patches, Y);
    k_finalize<<<1, 128>>>();
    k_out<<<4096, 128>>>(patches, Y, out);
}

// round 6
// speedup vs baseline: 1.1522x; 1.1522x over previous
#include <cuda_runtime.h>

// ============================================================================
// SphericalHarmonicsGaussianKernels
//   patches: (8, 2048, 32, 3) fp32   -> d_in[0]
//   Y:       (16, 20) fp32           -> d_in[1]
//   out:     (8, 2048, 32, 16, 4) fp32
//
// R6 = R4/R5 resubmitted (both hit broker-level container flakes, never
// measured; identical-source precedent: R1 flaked, passed verbatim in R2):
//   k_reduce: occupancy fix (1024 blocks, 2 pts/thread, 16 lanes/v).
//             R3's 256-block grid gave 3.5 warps/SMSP -> latency-bound ~55us.
//   k_out:    stage only sh[16]+shn[4] (80B/pt) instead of the full 256B
//             tile; products computed in store phase. L1 wavefronts -30%,
//             smem 34KB -> ~12KB per block.
// ============================================================================

__device__ float g_acc[128];                   // [b][l*4+s]
__device__ __align__(16) float g_ninv[128];    // [b][l*4+s]

// ---------------------------------------------------------------------------
// Per-point evaluation. sY = Y in shared memory, row-major [16][20].
// Monomial order (i=x-exp, lexicographic):
//  0:1  1:z  2:z2  3:z3  4:y  5:yz  6:yz2  7:y2  8:y2z  9:y3
// 10:x 11:xz 12:xz2 13:xy 14:xyz 15:xy2 16:x2 17:x2z 18:x2y 19:x3
// ---------------------------------------------------------------------------
__device__ __forceinline__ void point_eval(const float* __restrict__ sY,
                                           float x, float y, float z,
                                           float sh[16], float shn[4]) {
    float r2   = fmaf(x, x, fmaf(y, y, z * z));
    float dist = sqrtf(r2);
    float inv  = 1.0f / fmaxf(dist, 1e-6f);
    float nx = -x * inv, ny = -y * inv, nz = -z * inv;

    float mono[20];
    mono[0]  = 1.0f;
    mono[1]  = nz;
    mono[2]  = nz * nz;
    mono[3]  = mono[2] * nz;
    mono[4]  = ny;
    mono[5]  = ny * nz;
    mono[6]  = ny * mono[2];
    mono[7]  = ny * ny;
    mono[8]  = mono[7] * nz;
    mono[9]  = mono[7] * ny;
    mono[10] = nx;
    mono[11] = nx * nz;
    mono[12] = nx * mono[2];
    mono[13] = nx * ny;
    mono[14] = mono[13] * nz;
    mono[15] = nx * mono[7];
    mono[16] = nx * nx;
    mono[17] = mono[16] * nz;
    mono[18] = mono[16] * ny;
    mono[19] = mono[16] * nx;

    #pragma unroll
    for (int m = 0; m < 16; m++) {
        float a = sY[m * 20];                 // mono[0] == 1
        #pragma unroll
        for (int t = 1; t < 20; t++)
            a = fmaf(sY[m * 20 + t], mono[t], a);
        sh[m] = a;
    }

    float e[4];
    float ssum = 0.0f;
    #pragma unroll
    for (int s = 0; s < 4; s++) {
        float d = dist - (float)s * (1.0f / 3.0f);
        e[s] = __expf(-16.0f * d * d);
        ssum += e[s];
    }
    float w = 1.0f / fmaxf(ssum, 1e-6f);
    if (dist > 1.0f) w = 0.0f;                // mask AFTER normalization (ref order)
    #pragma unroll
    for (int s = 0; s < 4; s++) shn[s] = e[s] * w;
}

// ---------------------------------------------------------------------------
__global__ void k_zero() {
    g_acc[threadIdx.x] = 0.0f;                // 128 threads
}

// ---------------------------------------------------------------------------
// k_reduce: 1024 blocks x 256 threads; 2 points/thread. Warp covers 2 v's
// (16 lanes each). Butterfly over off=1,2,4,8 within each 16-lane group.
// b = blockIdx.x >> 7 (128 blocks per batch, batch-aligned).
// ---------------------------------------------------------------------------
__global__ __launch_bounds__(256) void k_reduce(const float* __restrict__ patches,
                                                const float* __restrict__ Y) {
    __shared__ float sY[320];
    __shared__ float bacc[16];
    int tid = threadIdx.x;
    if (tid < 16)  bacc[tid] = 0.0f;
    for (int i = tid; i < 320; i += 256) sY[i] = Y[i];
    __syncthreads();

    int warp = tid >> 5;
    int lane = tid & 31;
    int v    = blockIdx.x * 16 + warp * 2 + (lane >> 4);
    int sub  = lane & 15;

    // 2 points = 6 floats, 8B-aligned: float offset v*96 + sub*6
    const float2* pb = (const float2*)patches + (size_t)v * 48 + sub * 3;
    float2 a0 = pb[0], a1 = pb[1], a2 = pb[2];

    float c[16];
    #pragma unroll
    for (int i = 0; i < 16; i++) c[i] = 0.0f;

    float px[2] = { a0.x, a1.y };
    float py[2] = { a0.y, a2.x };
    float pz[2] = { a1.x, a2.y };

    #pragma unroll
    for (int j = 0; j < 2; j++) {
        float sh[16], shn[4];
        point_eval(sY, px[j], py[j], pz[j], sh, shn);

        float q[4];
        q[0] = sh[0] * sh[0];
        q[1] = fmaf(sh[1], sh[1], fmaf(sh[2], sh[2], sh[3] * sh[3]));
        q[2] = fmaf(sh[4], sh[4], fmaf(sh[5], sh[5],
               fmaf(sh[6], sh[6], fmaf(sh[7], sh[7], sh[8] * sh[8]))));
        q[3] = fmaf(sh[9],  sh[9],  fmaf(sh[10], sh[10],
               fmaf(sh[11], sh[11], fmaf(sh[12], sh[12],
               fmaf(sh[13], sh[13], fmaf(sh[14], sh[14], sh[15] * sh[15]))))));

        float s2[4];
        #pragma unroll
        for (int s = 0; s < 4; s++) s2[s] = shn[s] * shn[s];
        #pragma unroll
        for (int l = 0; l < 4; l++)
            #pragma unroll
            for (int s = 0; s < 4; s++)
                c[l * 4 + s] = fmaf(q[l], s2[s], c[l * 4 + s]);
    }

    // sum over the 16 lanes of this v (xor stays within the 16-lane group)
    #pragma unroll
    for (int off = 1; off <= 8; off <<= 1) {
        #pragma unroll
        for (int i = 0; i < 16; i++)
            c[i] += __shfl_xor_sync(0xffffffffu, c[i], off);
    }

    if (sub == 0) {                           // lanes 0 and 16
        #pragma unroll
        for (int i = 0; i < 16; i++)
            atomicAdd(&bacc[i], sqrtf(c[i]));   // sqrt per v, BEFORE mean over v
    }
    __syncthreads();

    if (tid < 16) {
        int b = blockIdx.x >> 7;
        atomicAdd(&g_acc[b * 16 + tid], bacc[tid]);
    }
}

__global__ void k_finalize() {
    int t = threadIdx.x;                      // 128 threads
    float ml = g_acc[t] * (1.0f / 2048.0f);
    g_ninv[t] = 1.0f / fmaxf(ml, 1e-8f);
}

// ---------------------------------------------------------------------------
// k_out: 4096 blocks x 128 threads. Phase 1: thread computes sh[16]+shn[4]
// for its point, stages 80B in smem. Phase 2: warp streams its 32x16 float4
// tile coalesced, computing sh*(shn*ninv) on the fly.
// b = blockIdx.x >> 9 (512 blocks per batch, batch-aligned).
// ---------------------------------------------------------------------------
__global__ __launch_bounds__(128) void k_out(const float* __restrict__ patches,
                                             const float* __restrict__ Y,
                                             float* __restrict__ out) {
    __shared__ float  sY[320];
    __shared__ float4 sninv4[4];              // [l] -> (s0..s3)
    __shared__ float4 s4[4][4 * 33];          // [warp][c*33 + pt]: sh[4c..4c+3]
    __shared__ float4 sn4[4][32];             // [warp][pt]: shn

    int tid = threadIdx.x;
    if (tid < 4) {
        int b = blockIdx.x >> 9;
        sninv4[tid] = ((const float4*)g_ninv)[b * 4 + tid];
    }
    for (int i = tid; i < 320; i += 128) sY[i] = Y[i];
    __syncthreads();

    int warp = tid >> 5;
    int lane = tid & 31;
    int pt   = blockIdx.x * 128 + tid;

    const float* p = patches + (size_t)pt * 3;
    float x = p[0], y = p[1], z = p[2];

    float sh[16], shn[4];
    point_eval(sY, x, y, z, sh, shn);

    // ---- phase 1: stage 80B ----
    s4[warp][0 * 33 + lane] = make_float4(sh[0],  sh[1],  sh[2],  sh[3]);
    s4[warp][1 * 33 + lane] = make_float4(sh[4],  sh[5],  sh[6],  sh[7]);
    s4[warp][2 * 33 + lane] = make_float4(sh[8],  sh[9],  sh[10], sh[11]);
    s4[warp][3 * 33 + lane] = make_float4(sh[12], sh[13], sh[14], sh[15]);
    sn4[warp][lane] = make_float4(shn[0], shn[1], shn[2], shn[3]);
    __syncwarp();

    // ---- phase 2: coalesced stream ----
    int m = lane & 15;
    int l = (m == 0) ? 0 : (m < 4) ? 1 : (m < 9) ? 2 : 3;
    float4 nv = sninv4[l];
    int hi = lane >> 4;                       // 0 or 1

    float4* dst = (float4*)out + ((size_t)blockIdx.x * 128 + warp * 32) * 16;
    #pragma unroll
    for (int it = 0; it < 16; it++) {
        int pp = 2 * it + hi;                 // point within warp tile
        float  shv = ((const float*)&s4[warp][(m >> 2) * 33 + pp])[m & 3];
        float4 sn  = sn4[warp][pp];
        float4 v;
        v.x = shv * (sn.x * nv.x);
        v.y = shv * (sn.y * nv.y);
        v.z = shv * (sn.z * nv.z);
        v.w = shv * (sn.w * nv.w);
        dst[it * 32 + lane] = v;
    }
}

// ---------------------------------------------------------------------------
extern "C" void kernel_launch(void* const* d_in, const int* in_sizes, int n_in,
                              void* d_out, int out_size) {
    const float* patches = (const float*)d_in[0];
    const float* Y       = (const float*)d_in[1];
    float*       out     = (float*)d_out;

    k_zero<<<1, 128>>>();
    k_reduce<<<1024, 256>>>(patches, Y);
    k_finalize<<<1, 128>>>();
    k_out<<<4096, 128>>>(patches, Y, out);
}

// round 7
// speedup vs baseline: 1.7589x; 1.5265x over previous
#include <cuda_runtime.h>

// ============================================================================
// SphericalHarmonicsGaussianKernels
//   patches: (8, 2048, 32, 3) fp32   -> d_in[0]
//   Y:       (16, 20) fp32           -> d_in[1]
//   out:     (8, 2048, 32, 16, 4) fp32
//
// R7 changes vs R6 (78.4us; k_out 31.8, k_reduce ~40):
//   k_reduce: rebuilt. 1 pt/thread (2048x256), q[4] accumulated on the fly
//             (no sh[16] array -> ~50 regs, was ~130 -> 1 block/SM), and a
//             vector-split butterfly: 16 SHFL total instead of 80.
//   k_out:    stage row stride 33->34 float4 kills the 2-way bank
//             degeneracy (16c mod 32 ∈ {0,16}) in phase-2 scalar LDS.
// ============================================================================

__device__ float g_acc[128];                   // [b][l*4+s]
__device__ __align__(16) float g_ninv[128];    // [b][l*4+s]

// ---------------------------------------------------------------------------
// Monomial order (i=x-exp, lexicographic):
//  0:1  1:z  2:z2  3:z3  4:y  5:yz  6:yz2  7:y2  8:y2z  9:y3
// 10:x 11:xz 12:xz2 13:xy 14:xyz 15:xy2 16:x2 17:x2z 18:x2y 19:x3
// ---------------------------------------------------------------------------
__device__ __forceinline__ void make_mono(float x, float y, float z,
                                          float& dist, float mono[20]) {
    float r2   = fmaf(x, x, fmaf(y, y, z * z));
    dist       = sqrtf(r2);
    float inv  = 1.0f / fmaxf(dist, 1e-6f);
    float nx = -x * inv, ny = -y * inv, nz = -z * inv;

    mono[0]  = 1.0f;
    mono[1]  = nz;
    mono[2]  = nz * nz;
    mono[3]  = mono[2] * nz;
    mono[4]  = ny;
    mono[5]  = ny * nz;
    mono[6]  = ny * mono[2];
    mono[7]  = ny * ny;
    mono[8]  = mono[7] * nz;
    mono[9]  = mono[7] * ny;
    mono[10] = nx;
    mono[11] = nx * nz;
    mono[12] = nx * mono[2];
    mono[13] = nx * ny;
    mono[14] = mono[13] * nz;
    mono[15] = nx * mono[7];
    mono[16] = nx * nx;
    mono[17] = mono[16] * nz;
    mono[18] = mono[16] * ny;
    mono[19] = mono[16] * nx;
}

__device__ __forceinline__ float dot20(const float* __restrict__ sY, int m,
                                       const float mono[20]) {
    float a = sY[m * 20];                     // mono[0] == 1
    #pragma unroll
    for (int t = 1; t < 20; t++)
        a = fmaf(sY[m * 20 + t], mono[t], a);
    return a;
}

__device__ __forceinline__ void shells_eval(float dist, float shn[4]) {
    float e[4];
    float ssum = 0.0f;
    #pragma unroll
    for (int s = 0; s < 4; s++) {
        float d = dist - (float)s * (1.0f / 3.0f);
        e[s] = __expf(-16.0f * d * d);
        ssum += e[s];
    }
    float w = 1.0f / fmaxf(ssum, 1e-6f);
    if (dist > 1.0f) w = 0.0f;                // mask AFTER normalization (ref order)
    #pragma unroll
    for (int s = 0; s < 4; s++) shn[s] = e[s] * w;
}

// ---------------------------------------------------------------------------
__global__ void k_zero() {
    g_acc[threadIdx.x] = 0.0f;                // 128 threads
}

// ---------------------------------------------------------------------------
// k_reduce: 2048 blocks x 256 threads; 1 point/thread; warp = one v.
// q[4] accumulated on the fly (no sh[16] kept). Vector-split butterfly:
// each stage keeps half the vector, exchanges the other half (16 SHFL).
// After stages off=16,8,4,2 lane holds component idx=(lane>>1)&15; off=1
// merges the duplicate pair. b = blockIdx.x >> 8.
// ---------------------------------------------------------------------------
__global__ __launch_bounds__(256) void k_reduce(const float* __restrict__ patches,
                                                const float* __restrict__ Y) {
    __shared__ float sY[320];
    __shared__ float bacc[16];
    int tid = threadIdx.x;
    if (tid < 16)  bacc[tid] = 0.0f;
    for (int i = tid; i < 320; i += 256) sY[i] = Y[i];
    __syncthreads();

    int lane = tid & 31;
    int pt   = blockIdx.x * 256 + tid;

    const float* p = patches + (size_t)pt * 3;
    float x = p[0], y = p[1], z = p[2];

    float dist, mono[20];
    make_mono(x, y, z, dist, mono);

    // degree-grouped squared sums, sh values not kept
    float q0, q1 = 0.0f, q2 = 0.0f, q3 = 0.0f;
    { float a = dot20(sY, 0, mono); q0 = a * a; }
    #pragma unroll
    for (int m = 1; m < 4; m++)  { float a = dot20(sY, m, mono); q1 = fmaf(a, a, q1); }
    #pragma unroll
    for (int m = 4; m < 9; m++)  { float a = dot20(sY, m, mono); q2 = fmaf(a, a, q2); }
    #pragma unroll
    for (int m = 9; m < 16; m++) { float a = dot20(sY, m, mono); q3 = fmaf(a, a, q3); }

    float shn[4];
    shells_eval(dist, shn);
    float s2[4];
    #pragma unroll
    for (int s = 0; s < 4; s++) s2[s] = shn[s] * shn[s];

    float c[16];
    #pragma unroll
    for (int s = 0; s < 4; s++) {
        c[0 * 4 + s] = q0 * s2[s];
        c[1 * 4 + s] = q1 * s2[s];
        c[2 * 4 + s] = q2 * s2[s];
        c[3 * 4 + s] = q3 * s2[s];
    }

    // ---- vector-split butterfly (16 SHFL) ----
    float d8[8];
    #pragma unroll
    for (int i = 0; i < 8; i++) {
        float send = (lane & 16) ? c[i] : c[i + 8];
        float recv = __shfl_xor_sync(0xffffffffu, send, 16);
        d8[i] = ((lane & 16) ? c[i + 8] : c[i]) + recv;
    }
    float d4[4];
    #pragma unroll
    for (int i = 0; i < 4; i++) {
        float send = (lane & 8) ? d8[i] : d8[i + 4];
        float recv = __shfl_xor_sync(0xffffffffu, send, 8);
        d4[i] = ((lane & 8) ? d8[i + 4] : d8[i]) + recv;
    }
    float d2[2];
    #pragma unroll
    for (int i = 0; i < 2; i++) {
        float send = (lane & 4) ? d4[i] : d4[i + 2];
        float recv = __shfl_xor_sync(0xffffffffu, send, 4);
        d2[i] = ((lane & 4) ? d4[i + 2] : d4[i]) + recv;
    }
    float d1;
    {
        float send = (lane & 2) ? d2[0] : d2[1];
        float recv = __shfl_xor_sync(0xffffffffu, send, 2);
        d1 = ((lane & 2) ? d2[1] : d2[0]) + recv;
    }
    d1 += __shfl_xor_sync(0xffffffffu, d1, 1);

    if (!(lane & 1)) {
        int idx = (lane >> 1) & 15;           // component this lane holds
        atomicAdd(&bacc[idx], sqrtf(d1));     // sqrt per v, BEFORE mean over v
    }
    __syncthreads();

    if (tid < 16) {
        int b = blockIdx.x >> 8;              // 256 blocks per batch
        atomicAdd(&g_acc[b * 16 + tid], bacc[tid]);
    }
}

__global__ void k_finalize() {
    int t = threadIdx.x;                      // 128 threads
    float ml = g_acc[t] * (1.0f / 2048.0f);
    g_ninv[t] = 1.0f / fmaxf(ml, 1e-8f);
}

// ---------------------------------------------------------------------------
// k_out: 4096 blocks x 128 threads. Phase 1: thread computes sh[16]+shn[4],
// stages 80B in smem (row stride 34 float4 -> conflict-free phase 2).
// Phase 2: warp streams its 32x16 float4 tile coalesced.
// b = blockIdx.x >> 9.
// ---------------------------------------------------------------------------
__global__ __launch_bounds__(128) void k_out(const float* __restrict__ patches,
                                             const float* __restrict__ Y,
                                             float* __restrict__ out) {
    __shared__ float  sY[320];
    __shared__ float4 sninv4[4];              // [l] -> (s0..s3)
    __shared__ float4 s4[4][4 * 34];          // [warp][c*34 + pt]: sh[4c..4c+3]
    __shared__ float4 sn4[4][32];             // [warp][pt]: shn

    int tid = threadIdx.x;
    if (tid < 4) {
        int b = blockIdx.x >> 9;
        sninv4[tid] = ((const float4*)g_ninv)[b * 4 + tid];
    }
    for (int i = tid; i < 320; i += 128) sY[i] = Y[i];
    __syncthreads();

    int warp = tid >> 5;
    int lane = tid & 31;
    int pt   = blockIdx.x * 128 + tid;

    const float* p = patches + (size_t)pt * 3;
    float x = p[0], y = p[1], z = p[2];

    float dist, mono[20];
    make_mono(x, y, z, dist, mono);

    float sh[16];
    #pragma unroll
    for (int m = 0; m < 16; m++) sh[m] = dot20(sY, m, mono);

    float shn[4];
    shells_eval(dist, shn);

    // ---- phase 1: stage 80B ----
    s4[warp][0 * 34 + lane] = make_float4(sh[0],  sh[1],  sh[2],  sh[3]);
    s4[warp][1 * 34 + lane] = make_float4(sh[4],  sh[5],  sh[6],  sh[7]);
    s4[warp][2 * 34 + lane] = make_float4(sh[8],  sh[9],  sh[10], sh[11]);
    s4[warp][3 * 34 + lane] = make_float4(sh[12], sh[13], sh[14], sh[15]);
    sn4[warp][lane] = make_float4(shn[0], shn[1], shn[2], shn[3]);
    __syncwarp();

    // ---- phase 2: coalesced stream ----
    int m = lane & 15;
    int l = (m == 0) ? 0 : (m < 4) ? 1 : (m < 9) ? 2 : 3;
    float4 nv = sninv4[l];
    int hi = lane >> 4;                       // 0 or 1

    float4* dst = (float4*)out + ((size_t)blockIdx.x * 128 + warp * 32) * 16;
    #pragma unroll
    for (int it = 0; it < 16; it++) {
        int pp = 2 * it + hi;                 // point within warp tile
        float  shv = ((const float*)&s4[warp][(m >> 2) * 34 + pp])[m & 3];
        float4 sn  = sn4[warp][pp];
        float4 v;
        v.x = shv * (sn.x * nv.x);
        v.y = shv * (sn.y * nv.y);
        v.z = shv * (sn.z * nv.z);
        v.w = shv * (sn.w * nv.w);
        dst[it * 32 + lane] = v;
    }
}

// ---------------------------------------------------------------------------
extern "C" void kernel_launch(void* const* d_in, const int* in_sizes, int n_in,
                              void* d_out, int out_size) {
    const float* patches = (const float*)d_in[0];
    const float* Y       = (const float*)d_in[1];
    float*       out     = (float*)d_out;

    k_zero<<<1, 128>>>();
    k_reduce<<<2048, 256>>>(patches, Y);
    k_finalize<<<1, 128>>>();
    k_out<<<4096, 128>>>(patches, Y, out);
}